// round 1
// baseline (speedup 1.0000x reference)
#include <cuda_runtime.h>
#include <cuda_bf16.h>
#include <math.h>

#define NN 50000
#define NE 800000
#define ET (NE + NN)      // edges + self loops
#define F1 128            // layer1 feature dim (H*C = 2*64)
#define C2 64             // layer2 out dim
#define NG 512
#define NEG_SLOPE 0.2f

// ---------------- scratch (device globals; no allocation allowed) ------------
__device__ __align__(16) float g_h1[NN * F1];     // x @ W1
__device__ __align__(16) float g_out1[NN * F1];   // layer1 aggregated output
__device__ __align__(16) float g_h2[NN * C2];     // relu(out1+b1) @ W2
__device__ __align__(16) float g_out2[NN * C2];   // layer2 aggregated output
__device__ __align__(16) float g_e1[ET * 2];      // per-edge e then ex (2 heads)
__device__ __align__(16) float g_e2[ET];          // per-edge e then ex (1 head)
__device__ __align__(16) int2  g_sd[ET];          // decoded (src,dst)
__device__ __align__(16) float g_as1[NN * 2], g_ad1[NN * 2];
__device__ __align__(16) float g_emax1[NN * 2], g_den1[NN * 2];
__device__ __align__(16) float g_as2[NN], g_ad2[NN];
__device__ __align__(16) float g_emax2[NN], g_den2[NN];
__device__ __align__(16) float g_pool[NG * C2];
__device__ __align__(16) float g_cnt[NG];
__device__ int g_is64;

// ---------------- helpers ----------------------------------------------------
__device__ __forceinline__ long long loadIdx(const void* p, long long i, int is64) {
    if (is64) return ((const long long*)p)[i];
    return (long long)((const int*)p)[i];
}

__device__ __forceinline__ void atomicMaxF(float* addr, float v) {
    if (v >= 0.f) atomicMax((int*)addr, __float_as_int(v));
    else          atomicMin((unsigned int*)addr, __float_as_uint(v));
}

__device__ __forceinline__ void redv4(float* dst, float a, float b, float c, float d) {
    asm volatile("red.global.add.v4.f32 [%0], {%1, %2, %3, %4};"
                 :: "l"(dst), "f"(a), "f"(b), "f"(c), "f"(d) : "memory");
}

__device__ __forceinline__ float lrelu(float x) { return x > 0.f ? x : NEG_SLOPE * x; }

// ---------------- dtype detection (int32 vs int64 indices) -------------------
__global__ void detect_k(const unsigned int* ei) {
    unsigned int any = 0;
    for (int i = 1; i < 2048; i += 2) any |= ei[i];   // high words if int64
    g_is64 = (any == 0) ? 1 : 0;
}

// ---------------- init --------------------------------------------------------
__global__ void init_k() {
    int i = blockIdx.x * blockDim.x + threadIdx.x;
    if (i < NN * F1) g_out1[i] = 0.f;
    if (i < NN * C2) g_out2[i] = 0.f;
    if (i < NN * 2) { g_den1[i] = 0.f; g_emax1[i] = -INFINITY; }
    if (i < NN)     { g_den2[i] = 0.f; g_emax2[i] = -INFINITY; }
    if (i < NG * C2) g_pool[i] = 0.f;
    if (i < NG)      g_cnt[i]  = 0.f;
}

// ---------------- GEMM (M x 128) @ (128 x NCOL) -------------------------------
template <int BM, int NCOL>
__device__ __forceinline__ void gemm_body(const float* __restrict__ A,
                                          const float* __restrict__ W,
                                          float* __restrict__ Cd) {
    constexpr int BK = 32, TM = 8, TN = 4;
    constexpr int TCOLS = NCOL / TN;
    __shared__ float xs[BM][BK];
    __shared__ float ws[BK][NCOL];
    const int tid  = threadIdx.x;
    const int row0 = blockIdx.x * BM;
    const int trow = tid / TCOLS;
    const int tcol = tid % TCOLS;
    float acc[TM][TN];
#pragma unroll
    for (int m = 0; m < TM; m++)
#pragma unroll
        for (int t = 0; t < TN; t++) acc[m][t] = 0.f;

    for (int kc = 0; kc < 128; kc += BK) {
        for (int i = tid; i < BM * (BK / 4); i += 256) {
            int r = i >> 3, c = i & 7;
            int gr = row0 + r;
            float4 v = make_float4(0.f, 0.f, 0.f, 0.f);
            if (gr < NN) v = *(const float4*)(A + (size_t)gr * 128 + kc + c * 4);
            *(float4*)&xs[r][c * 4] = v;
        }
        for (int i = tid; i < BK * (NCOL / 4); i += 256) {
            int r = i / (NCOL / 4), c = i % (NCOL / 4);
            *(float4*)&ws[r][c * 4] = *(const float4*)(W + (size_t)(kc + r) * NCOL + c * 4);
        }
        __syncthreads();
#pragma unroll
        for (int k = 0; k < BK; k++) {
            float4 wv = *(const float4*)&ws[k][tcol * 4];
#pragma unroll
            for (int m = 0; m < TM; m++) {
                float xv = xs[trow * TM + m][k];
                acc[m][0] += xv * wv.x;
                acc[m][1] += xv * wv.y;
                acc[m][2] += xv * wv.z;
                acc[m][3] += xv * wv.w;
            }
        }
        __syncthreads();
    }
#pragma unroll
    for (int m = 0; m < TM; m++) {
        int gr = row0 + trow * TM + m;
        if (gr < NN)
            *(float4*)(Cd + (size_t)gr * NCOL + tcol * 4) =
                make_float4(acc[m][0], acc[m][1], acc[m][2], acc[m][3]);
    }
}

__global__ void gemm1_k(const float* __restrict__ A, const float* __restrict__ W) {
    gemm_body<64, 128>(A, W, g_h1);
}
__global__ void gemm2_k(const float* __restrict__ W) {
    gemm_body<128, 64>(g_out1, W, g_h2);
}

// ---------------- alpha = <h, a> per (node, head) ------------------------------
__global__ void alpha1_k(const float* __restrict__ asrc, const float* __restrict__ adst) {
    int gw = (blockIdx.x * blockDim.x + threadIdx.x) >> 5;
    int lane = threadIdx.x & 31;
    if (gw >= NN * 2) return;
    int n = gw >> 1, hd = gw & 1;
    const float* hp = g_h1 + (size_t)n * 128 + hd * 64;
    float2 hv = *(const float2*)(hp + lane * 2);
    float2 sv = *(const float2*)(asrc + hd * 64 + lane * 2);
    float2 dv = *(const float2*)(adst + hd * 64 + lane * 2);
    float ps = hv.x * sv.x + hv.y * sv.y;
    float pd = hv.x * dv.x + hv.y * dv.y;
#pragma unroll
    for (int o = 16; o; o >>= 1) {
        ps += __shfl_xor_sync(0xffffffffu, ps, o);
        pd += __shfl_xor_sync(0xffffffffu, pd, o);
    }
    if (!lane) { g_as1[n * 2 + hd] = ps; g_ad1[n * 2 + hd] = pd; }
}

__global__ void alpha2_k(const float* __restrict__ asrc, const float* __restrict__ adst) {
    int gw = (blockIdx.x * blockDim.x + threadIdx.x) >> 5;
    int lane = threadIdx.x & 31;
    if (gw >= NN) return;
    const float* hp = g_h2 + (size_t)gw * 64;
    float2 hv = *(const float2*)(hp + lane * 2);
    float2 sv = *(const float2*)(asrc + lane * 2);
    float2 dv = *(const float2*)(adst + lane * 2);
    float ps = hv.x * sv.x + hv.y * sv.y;
    float pd = hv.x * dv.x + hv.y * dv.y;
#pragma unroll
    for (int o = 16; o; o >>= 1) {
        ps += __shfl_xor_sync(0xffffffffu, ps, o);
        pd += __shfl_xor_sync(0xffffffffu, pd, o);
    }
    if (!lane) { g_as2[gw] = ps; g_ad2[gw] = pd; }
}

// ---------------- layer 1 edge passes ------------------------------------------
__global__ void passA1_k(const void* __restrict__ ei) {
    int e = blockIdx.x * blockDim.x + threadIdx.x;
    if (e >= ET) return;
    int s, d;
    if (e < NE) {
        int is64 = g_is64;
        s = (int)loadIdx(ei, e, is64);
        d = (int)loadIdx(ei, (long long)NE + e, is64);
    } else {
        s = d = e - NE;
    }
    g_sd[e] = make_int2(s, d);
    float2 as = *(const float2*)(g_as1 + s * 2);
    float2 ad = *(const float2*)(g_ad1 + d * 2);
    float e0 = lrelu(as.x + ad.x);
    float e1 = lrelu(as.y + ad.y);
    ((float2*)g_e1)[e] = make_float2(e0, e1);
    atomicMaxF(g_emax1 + d * 2, e0);
    atomicMaxF(g_emax1 + d * 2 + 1, e1);
}

__global__ void passB1_k() {
    int e = blockIdx.x * blockDim.x + threadIdx.x;
    if (e >= ET) return;
    int2 sd = g_sd[e];
    float2 ev = ((const float2*)g_e1)[e];
    float2 mx = *(const float2*)(g_emax1 + sd.y * 2);
    float x0 = __expf(ev.x - mx.x);
    float x1 = __expf(ev.y - mx.y);
    ((float2*)g_e1)[e] = make_float2(x0, x1);
    atomicAdd(g_den1 + sd.y * 2, x0);
    atomicAdd(g_den1 + sd.y * 2 + 1, x1);
}

__global__ void passC1_k() {
    int t = blockIdx.x * blockDim.x + threadIdx.x;
    int e = t >> 5, lane = t & 31;
    if (e >= ET) return;
    int2 sd = g_sd[e];
    float2 ex = ((const float2*)g_e1)[e];
    float2 dn = *(const float2*)(g_den1 + sd.y * 2);
    float coef = (lane < 16) ? (ex.x / dn.x) : (ex.y / dn.y);
    float4 hv = *(const float4*)(g_h1 + (size_t)sd.x * 128 + lane * 4);
    float* dst = g_out1 + (size_t)sd.y * 128 + lane * 4;
    redv4(dst, hv.x * coef, hv.y * coef, hv.z * coef, hv.w * coef);
}

__global__ void relubias1_k(const float* __restrict__ b1) {
    int i = blockIdx.x * blockDim.x + threadIdx.x;
    if (i >= NN * F1) return;
    g_out1[i] = fmaxf(g_out1[i] + b1[i & 127], 0.f);
}

// ---------------- layer 2 edge passes ------------------------------------------
__global__ void passA2_k() {
    int e = blockIdx.x * blockDim.x + threadIdx.x;
    if (e >= ET) return;
    int2 sd = g_sd[e];
    float ev = lrelu(g_as2[sd.x] + g_ad2[sd.y]);
    g_e2[e] = ev;
    atomicMaxF(g_emax2 + sd.y, ev);
}

__global__ void passB2_k() {
    int e = blockIdx.x * blockDim.x + threadIdx.x;
    if (e >= ET) return;
    int2 sd = g_sd[e];
    float x = __expf(g_e2[e] - g_emax2[sd.y]);
    g_e2[e] = x;
    atomicAdd(g_den2 + sd.y, x);
}

__global__ void passC2_k() {
    int t = blockIdx.x * blockDim.x + threadIdx.x;
    int e = t >> 4, q = t & 15;
    if (e >= ET) return;
    int2 sd = g_sd[e];
    float coef = g_e2[e] / g_den2[sd.y];
    float4 hv = *(const float4*)(g_h2 + (size_t)sd.x * 64 + q * 4);
    float* dst = g_out2 + (size_t)sd.y * 64 + q * 4;
    redv4(dst, hv.x * coef, hv.y * coef, hv.z * coef, hv.w * coef);
}

__global__ void relubias2_k(const float* __restrict__ b2) {
    int i = blockIdx.x * blockDim.x + threadIdx.x;
    if (i >= NN * C2) return;
    g_out2[i] = fmaxf(g_out2[i] + b2[i & 63], 0.f);
}

// ---------------- pooling + FC + log_softmax -----------------------------------
__global__ void pool_k(const void* __restrict__ batch) {
    int t = blockIdx.x * blockDim.x + threadIdx.x;
    int n = t >> 5, lane = t & 31;
    if (n >= NN) return;
    int b = (int)loadIdx(batch, n, g_is64);
    float v0 = g_out2[(size_t)n * 64 + lane];
    float v1 = g_out2[(size_t)n * 64 + 32 + lane];
    atomicAdd(g_pool + (size_t)b * 64 + lane, v0);
    atomicAdd(g_pool + (size_t)b * 64 + 32 + lane, v1);
    if (!lane) atomicAdd(g_cnt + b, 1.f);
}

__global__ void final_k(const float* __restrict__ fcW, const float* __restrict__ fcb,
                        float* __restrict__ out) {
    int gw = (blockIdx.x * blockDim.x + threadIdx.x) >> 5;
    int lane = threadIdx.x & 31;
    if (gw >= NG) return;
    float inv = 1.f / fmaxf(g_cnt[gw], 1.f);
    float p0 = g_pool[(size_t)gw * 64 + lane] * inv;
    float p1 = g_pool[(size_t)gw * 64 + 32 + lane] * inv;
    float l0 = p0 * fcW[lane * 2]     + p1 * fcW[(lane + 32) * 2];
    float l1 = p0 * fcW[lane * 2 + 1] + p1 * fcW[(lane + 32) * 2 + 1];
#pragma unroll
    for (int o = 16; o; o >>= 1) {
        l0 += __shfl_xor_sync(0xffffffffu, l0, o);
        l1 += __shfl_xor_sync(0xffffffffu, l1, o);
    }
    if (!lane) {
        l0 += fcb[0];
        l1 += fcb[1];
        float m = fmaxf(l0, l1);
        float lse = m + logf(expf(l0 - m) + expf(l1 - m));
        out[gw * 2]     = l0 - lse;
        out[gw * 2 + 1] = l1 - lse;
    }
}

// ---------------- launch --------------------------------------------------------
extern "C" void kernel_launch(void* const* d_in, const int* in_sizes, int n_in,
                              void* d_out, int out_size) {
    const float* x     = (const float*)d_in[0];
    const void*  ei    = d_in[1];
    const void*  batch = d_in[2];
    const float* W1    = (const float*)d_in[3];
    const float* asrc1 = (const float*)d_in[4];
    const float* adst1 = (const float*)d_in[5];
    const float* b1    = (const float*)d_in[6];
    const float* W2    = (const float*)d_in[7];
    const float* asrc2 = (const float*)d_in[8];
    const float* adst2 = (const float*)d_in[9];
    const float* b2    = (const float*)d_in[10];
    const float* fcW   = (const float*)d_in[11];
    const float* fcb   = (const float*)d_in[12];
    float* out = (float*)d_out;

    detect_k<<<1, 1>>>((const unsigned int*)ei);
    init_k<<<(NN * F1 + 255) / 256, 256>>>();

    // layer 1
    gemm1_k<<<(NN + 63) / 64, 256>>>(x, W1);
    alpha1_k<<<(NN * 2 * 32 + 255) / 256, 256>>>(asrc1, adst1);
    passA1_k<<<(ET + 255) / 256, 256>>>(ei);
    passB1_k<<<(ET + 255) / 256, 256>>>();
    passC1_k<<<(ET * 32 + 255) / 256, 256>>>();
    relubias1_k<<<(NN * F1 + 255) / 256, 256>>>(b1);

    // layer 2
    gemm2_k<<<(NN + 127) / 128, 256>>>(W2);
    alpha2_k<<<(NN * 32 + 255) / 256, 256>>>(asrc2, adst2);
    passA2_k<<<(ET + 255) / 256, 256>>>();
    passB2_k<<<(ET + 255) / 256, 256>>>();
    passC2_k<<<(ET * 16 + 255) / 256, 256>>>();
    relubias2_k<<<(NN * C2 + 255) / 256, 256>>>(b2);

    // pool + classifier
    pool_k<<<(NN * 32 + 255) / 256, 256>>>(batch);
    final_k<<<(NG * 32 + 255) / 256, 256>>>(fcW, fcb, out);
}

// round 2
// speedup vs baseline: 1.6918x; 1.6918x over previous
#include <cuda_runtime.h>
#include <cuda_bf16.h>
#include <math.h>

#define NN 50000
#define NE 800000
#define F1 128
#define C2 64
#define NG 512
#define NEG_SLOPE 0.2f
#define NB1 ((NN + 1023) / 1024)

typedef unsigned long long ull;

// ---------------- scratch ----------------
__device__ __align__(16) float g_h1[NN * F1];
__device__ __align__(16) float g_out1[NN * F1];
__device__ __align__(16) float g_h2[NN * C2];
__device__ __align__(16) float g_out2[NN * C2];
__device__ __align__(16) float g_as1[NN * 2], g_ad1[NN * 2];
__device__ __align__(16) float g_as2[NN], g_ad2[NN];
__device__ __align__(16) float g_pool[NG * C2];
__device__ __align__(16) float g_cnt[NG];
__device__ int g_hist[NN];
__device__ int g_scan[NN];
__device__ int g_cursor[NN];
__device__ int g_off[NN + 1];
__device__ int g_blk[NB1];
__device__ int g_csr[NE];
__device__ int g_is64;

// ---------------- helpers ----------------
__device__ __forceinline__ float lrelu(float x) { return x > 0.f ? x : NEG_SLOPE * x; }

__device__ __forceinline__ ull pack2(float x, float y) {
    ull r; asm("mov.b64 %0, {%1, %2};" : "=l"(r) : "f"(x), "f"(y)); return r;
}
__device__ __forceinline__ void unpack2(ull p, float& x, float& y) {
    asm("mov.b64 {%0, %1}, %2;" : "=f"(x), "=f"(y) : "l"(p));
}
__device__ __forceinline__ void ffma2(ull& acc, ull a, ull b) {
    asm("fma.rn.f32x2 %0, %1, %2, %0;" : "+l"(acc) : "l"(a), "l"(b));
}

__device__ __forceinline__ long long loadIdx(const void* p, long long i, int is64) {
    if (is64) return ((const long long*)p)[i];
    return (long long)((const int*)p)[i];
}

// ---------------- dtype detection ----------------
__global__ void detect_k(const unsigned int* ei) {
    __shared__ unsigned int red;
    if (threadIdx.x == 0) red = 0u;
    __syncthreads();
    unsigned int any = 0;
    for (int i = 1 + 2 * threadIdx.x; i < 4096; i += 512) any |= ei[i];
#pragma unroll
    for (int o = 16; o; o >>= 1) any |= __shfl_xor_sync(0xffffffffu, any, o);
    if ((threadIdx.x & 31) == 0) atomicOr(&red, any);
    __syncthreads();
    if (threadIdx.x == 0) g_is64 = (red == 0u) ? 1 : 0;
}

// ---------------- init ----------------
__global__ void init_k() {
    int i = blockIdx.x * blockDim.x + threadIdx.x;
    if (i < NN) g_hist[i] = 0;
    if (i < NG * C2) g_pool[i] = 0.f;
    if (i < NG) g_cnt[i] = 0.f;
}

// ---------------- CSR build ----------------
__global__ void hist_k(const void* __restrict__ ei) {
    int e = blockIdx.x * blockDim.x + threadIdx.x;
    if (e >= NE) return;
    int d = (int)loadIdx(ei, (long long)NE + e, g_is64);
    atomicAdd(&g_hist[d], 1);
}

__global__ void scan1_k() {
    __shared__ int sm[1024];
    int i = blockIdx.x * 1024 + threadIdx.x;
    int v = (i < NN) ? g_hist[i] : 0;
    sm[threadIdx.x] = v;
    __syncthreads();
    for (int o = 1; o < 1024; o <<= 1) {
        int t = (threadIdx.x >= o) ? sm[threadIdx.x - o] : 0;
        __syncthreads();
        sm[threadIdx.x] += t;
        __syncthreads();
    }
    if (i < NN) g_scan[i] = sm[threadIdx.x];
    if (threadIdx.x == 1023) g_blk[blockIdx.x] = sm[1023];
}

__global__ void scan2_k() {
    if (threadIdx.x == 0) {
        int acc = 0;
        for (int b = 0; b < NB1; b++) { int t = g_blk[b]; g_blk[b] = acc; acc += t; }
    }
}

__global__ void scan3_k() {
    int i = blockIdx.x * 1024 + threadIdx.x;
    if (i >= NN) return;
    int inc = g_scan[i] + g_blk[blockIdx.x];
    g_off[i + 1] = inc;
    g_cursor[i] = inc - g_hist[i];
    if (i == 0) g_off[0] = 0;
}

__global__ void scatter_k(const void* __restrict__ ei) {
    int e = blockIdx.x * blockDim.x + threadIdx.x;
    if (e >= NE) return;
    int is64 = g_is64;
    int s = (int)loadIdx(ei, e, is64);
    int d = (int)loadIdx(ei, (long long)NE + e, is64);
    int pos = atomicAdd(&g_cursor[d], 1);
    g_csr[pos] = s;
}

// ---------------- GEMM: (M x 128) @ (128 x NCOL) via fma.rn.f32x2 ----------------
template <int NCOL>
__device__ __forceinline__ void gemm_body(const float* __restrict__ A,
                                          const float* __restrict__ W,
                                          float* __restrict__ Cd, int M) {
    constexpr int BM = 128, BK = 16;
    constexpr int TX = NCOL / 8;       // threads along col dim
    constexpr int NT = 16 * TX;        // total threads
    __shared__ float As[BK][BM];
    __shared__ float Ws[BK][NCOL];
    const int tid = threadIdx.x;
    const int trow = tid / TX, tcol = tid % TX;
    const int row0 = blockIdx.x * BM;
    ull acc[8][4];
#pragma unroll
    for (int m = 0; m < 8; m++)
#pragma unroll
        for (int p = 0; p < 4; p++) acc[m][p] = 0ull;

    for (int kc = 0; kc < 128; kc += BK) {
        for (int i = tid; i < BM * BK / 4; i += NT) {
            int r = i >> 2, q = i & 3;
            float4 v = make_float4(0.f, 0.f, 0.f, 0.f);
            int gr = row0 + r;
            if (gr < M) v = *(const float4*)(A + (size_t)gr * 128 + kc + q * 4);
            As[q * 4 + 0][r] = v.x;
            As[q * 4 + 1][r] = v.y;
            As[q * 4 + 2][r] = v.z;
            As[q * 4 + 3][r] = v.w;
        }
        for (int i = tid; i < BK * NCOL / 4; i += NT) {
            int r = i / (NCOL / 4), c = i % (NCOL / 4);
            *(float4*)&Ws[r][c * 4] = *(const float4*)(W + (size_t)(kc + r) * NCOL + c * 4);
        }
        __syncthreads();
#pragma unroll
        for (int k = 0; k < BK; k++) {
            float4 a0 = *(const float4*)&As[k][trow * 8];
            float4 a1 = *(const float4*)&As[k][trow * 8 + 4];
            float4 w0 = *(const float4*)&Ws[k][tcol * 8];
            float4 w1 = *(const float4*)&Ws[k][tcol * 8 + 4];
            ull wp[4] = {pack2(w0.x, w0.y), pack2(w0.z, w0.w),
                         pack2(w1.x, w1.y), pack2(w1.z, w1.w)};
            float av[8] = {a0.x, a0.y, a0.z, a0.w, a1.x, a1.y, a1.z, a1.w};
#pragma unroll
            for (int m = 0; m < 8; m++) {
                ull ap = pack2(av[m], av[m]);
#pragma unroll
                for (int p = 0; p < 4; p++) ffma2(acc[m][p], ap, wp[p]);
            }
        }
        __syncthreads();
    }
#pragma unroll
    for (int m = 0; m < 8; m++) {
        int gr = row0 + trow * 8 + m;
        if (gr >= M) continue;
        float o[8];
#pragma unroll
        for (int p = 0; p < 4; p++) unpack2(acc[m][p], o[2 * p], o[2 * p + 1]);
        *(float4*)(Cd + (size_t)gr * NCOL + tcol * 8) = make_float4(o[0], o[1], o[2], o[3]);
        *(float4*)(Cd + (size_t)gr * NCOL + tcol * 8 + 4) = make_float4(o[4], o[5], o[6], o[7]);
    }
}

__global__ void __launch_bounds__(256) gemm1_k(const float* __restrict__ A,
                                               const float* __restrict__ W) {
    gemm_body<128>(A, W, g_h1, NN);
}
__global__ void __launch_bounds__(128) gemm2_k(const float* __restrict__ W) {
    gemm_body<64>(g_out1, W, g_h2, NN);
}

// ---------------- alpha (node attention scalars) ----------------
__global__ void alpha1_k(const float* __restrict__ asrc, const float* __restrict__ adst) {
    int n = (blockIdx.x * blockDim.x + threadIdx.x) >> 5;
    int lane = threadIdx.x & 31;
    if (n >= NN) return;
    float4 h = *(const float4*)(g_h1 + (size_t)n * 128 + lane * 4);
    float4 s = *(const float4*)(asrc + lane * 4);   // [2][64] flattened == lane*4
    float4 d = *(const float4*)(adst + lane * 4);
    float ps = h.x * s.x + h.y * s.y + h.z * s.z + h.w * s.w;
    float pd = h.x * d.x + h.y * d.y + h.z * d.z + h.w * d.w;
#pragma unroll
    for (int o = 8; o; o >>= 1) {   // reduce within each 16-lane half (one head each)
        ps += __shfl_xor_sync(0xffffffffu, ps, o);
        pd += __shfl_xor_sync(0xffffffffu, pd, o);
    }
    if ((lane & 15) == 0) {
        int hd = lane >> 4;
        g_as1[n * 2 + hd] = ps;
        g_ad1[n * 2 + hd] = pd;
    }
}

__global__ void alpha2_k(const float* __restrict__ asrc, const float* __restrict__ adst) {
    int t = blockIdx.x * blockDim.x + threadIdx.x;
    int n = t >> 4, l = t & 15;
    if (n >= NN) return;
    float4 h = *(const float4*)(g_h2 + (size_t)n * 64 + l * 4);
    float4 s = *(const float4*)(asrc + l * 4);
    float4 d = *(const float4*)(adst + l * 4);
    float ps = h.x * s.x + h.y * s.y + h.z * s.z + h.w * s.w;
    float pd = h.x * d.x + h.y * d.y + h.z * d.z + h.w * d.w;
#pragma unroll
    for (int o = 8; o; o >>= 1) {
        ps += __shfl_xor_sync(0xffffffffu, ps, o);
        pd += __shfl_xor_sync(0xffffffffu, pd, o);
    }
    if (l == 0) { g_as2[n] = ps; g_ad2[n] = pd; }
}

// ---------------- fused softmax + aggregate, layer 1 (warp per dst) ----------------
__global__ void __launch_bounds__(256) edge1_k(const float* __restrict__ b1) {
    int d = (blockIdx.x * blockDim.x + threadIdx.x) >> 5;
    int lane = threadIdx.x & 31;
    if (d >= NN) return;
    int beg = g_off[d], end = g_off[d + 1];
    float2 ad = *(const float2*)(g_ad1 + d * 2);
    float2 asd = *(const float2*)(g_as1 + d * 2);

    // pass 1: denominators (no max shift needed; e is bounded)
    float s0 = 0.f, s1 = 0.f;
    for (int j = beg + lane; j < end; j += 32) {
        int s = g_csr[j];
        float2 as = *(const float2*)(g_as1 + s * 2);
        s0 += __expf(lrelu(as.x + ad.x));
        s1 += __expf(lrelu(as.y + ad.y));
    }
#pragma unroll
    for (int o = 16; o; o >>= 1) {
        s0 += __shfl_xor_sync(0xffffffffu, s0, o);
        s1 += __shfl_xor_sync(0xffffffffu, s1, o);
    }
    float x0s = __expf(lrelu(asd.x + ad.x));
    float x1s = __expf(lrelu(asd.y + ad.y));
    s0 += x0s; s1 += x1s;
    float inv0 = 1.f / s0, inv1 = 1.f / s1;

    // pass 2: aggregate. lanes 0-15 cover head0 cols, 16-31 head1 cols.
    float cself = (lane < 16) ? x0s * inv0 : x1s * inv1;
    float4 h = *(const float4*)(g_h1 + (size_t)d * 128 + lane * 4);
    float4 acc = make_float4(cself * h.x, cself * h.y, cself * h.z, cself * h.w);

    int j = beg;
    for (; j + 1 < end; j += 2) {
        int sA = g_csr[j], sB = g_csr[j + 1];
        float2 aA = *(const float2*)(g_as1 + sA * 2);
        float2 aB = *(const float2*)(g_as1 + sB * 2);
        float4 hA = *(const float4*)(g_h1 + (size_t)sA * 128 + lane * 4);
        float4 hB = *(const float4*)(g_h1 + (size_t)sB * 128 + lane * 4);
        float cA = (lane < 16) ? __expf(lrelu(aA.x + ad.x)) * inv0
                               : __expf(lrelu(aA.y + ad.y)) * inv1;
        float cB = (lane < 16) ? __expf(lrelu(aB.x + ad.x)) * inv0
                               : __expf(lrelu(aB.y + ad.y)) * inv1;
        acc.x += cA * hA.x + cB * hB.x;
        acc.y += cA * hA.y + cB * hB.y;
        acc.z += cA * hA.z + cB * hB.z;
        acc.w += cA * hA.w + cB * hB.w;
    }
    if (j < end) {
        int s = g_csr[j];
        float2 as = *(const float2*)(g_as1 + s * 2);
        float4 hv = *(const float4*)(g_h1 + (size_t)s * 128 + lane * 4);
        float c = (lane < 16) ? __expf(lrelu(as.x + ad.x)) * inv0
                              : __expf(lrelu(as.y + ad.y)) * inv1;
        acc.x += c * hv.x; acc.y += c * hv.y; acc.z += c * hv.z; acc.w += c * hv.w;
    }
    float4 b = *(const float4*)(b1 + lane * 4);
    *(float4*)(g_out1 + (size_t)d * 128 + lane * 4) =
        make_float4(fmaxf(acc.x + b.x, 0.f), fmaxf(acc.y + b.y, 0.f),
                    fmaxf(acc.z + b.z, 0.f), fmaxf(acc.w + b.w, 0.f));
}

// ---------------- fused softmax + aggregate, layer 2 ----------------
__global__ void __launch_bounds__(256) edge2_k(const float* __restrict__ b2) {
    int d = (blockIdx.x * blockDim.x + threadIdx.x) >> 5;
    int lane = threadIdx.x & 31;
    if (d >= NN) return;
    int beg = g_off[d], end = g_off[d + 1];
    float ad = g_ad2[d];

    float sum = 0.f;
    for (int j = beg + lane; j < end; j += 32)
        sum += __expf(lrelu(g_as2[g_csr[j]] + ad));
#pragma unroll
    for (int o = 16; o; o >>= 1) sum += __shfl_xor_sync(0xffffffffu, sum, o);
    float xs = __expf(lrelu(g_as2[d] + ad));
    sum += xs;
    float inv = 1.f / sum;

    float cself = xs * inv;
    float2 h = *(const float2*)(g_h2 + (size_t)d * 64 + lane * 2);
    float2 acc = make_float2(cself * h.x, cself * h.y);

    int j = beg;
    for (; j + 1 < end; j += 2) {
        int sA = g_csr[j], sB = g_csr[j + 1];
        float aA = g_as2[sA], aB = g_as2[sB];
        float2 hA = *(const float2*)(g_h2 + (size_t)sA * 64 + lane * 2);
        float2 hB = *(const float2*)(g_h2 + (size_t)sB * 64 + lane * 2);
        float cA = __expf(lrelu(aA + ad)) * inv;
        float cB = __expf(lrelu(aB + ad)) * inv;
        acc.x += cA * hA.x + cB * hB.x;
        acc.y += cA * hA.y + cB * hB.y;
    }
    if (j < end) {
        int s = g_csr[j];
        float2 hv = *(const float2*)(g_h2 + (size_t)s * 64 + lane * 2);
        float c = __expf(lrelu(g_as2[s] + ad)) * inv;
        acc.x += c * hv.x; acc.y += c * hv.y;
    }
    float2 b = *(const float2*)(b2 + lane * 2);
    *(float2*)(g_out2 + (size_t)d * 64 + lane * 2) =
        make_float2(fmaxf(acc.x + b.x, 0.f), fmaxf(acc.y + b.y, 0.f));
}

// ---------------- pooling + FC + log_softmax ----------------
__global__ void pool_k(const void* __restrict__ batch) {
    int t = blockIdx.x * blockDim.x + threadIdx.x;
    int n = t >> 5, lane = t & 31;
    if (n >= NN) return;
    int b = (int)loadIdx(batch, n, g_is64);
    float v0 = g_out2[(size_t)n * 64 + lane];
    float v1 = g_out2[(size_t)n * 64 + 32 + lane];
    atomicAdd(g_pool + (size_t)b * 64 + lane, v0);
    atomicAdd(g_pool + (size_t)b * 64 + 32 + lane, v1);
    if (!lane) atomicAdd(g_cnt + b, 1.f);
}

__global__ void final_k(const float* __restrict__ fcW, const float* __restrict__ fcb,
                        float* __restrict__ out) {
    int gw = (blockIdx.x * blockDim.x + threadIdx.x) >> 5;
    int lane = threadIdx.x & 31;
    if (gw >= NG) return;
    float inv = 1.f / fmaxf(g_cnt[gw], 1.f);
    float p0 = g_pool[(size_t)gw * 64 + lane] * inv;
    float p1 = g_pool[(size_t)gw * 64 + 32 + lane] * inv;
    float l0 = p0 * fcW[lane * 2] + p1 * fcW[(lane + 32) * 2];
    float l1 = p0 * fcW[lane * 2 + 1] + p1 * fcW[(lane + 32) * 2 + 1];
#pragma unroll
    for (int o = 16; o; o >>= 1) {
        l0 += __shfl_xor_sync(0xffffffffu, l0, o);
        l1 += __shfl_xor_sync(0xffffffffu, l1, o);
    }
    if (!lane) {
        l0 += fcb[0];
        l1 += fcb[1];
        float m = fmaxf(l0, l1);
        float lse = m + logf(expf(l0 - m) + expf(l1 - m));
        out[gw * 2] = l0 - lse;
        out[gw * 2 + 1] = l1 - lse;
    }
}

// ---------------- launch ----------------
extern "C" void kernel_launch(void* const* d_in, const int* in_sizes, int n_in,
                              void* d_out, int out_size) {
    const float* x = (const float*)d_in[0];
    const void* ei = d_in[1];
    const void* batch = d_in[2];
    const float* W1 = (const float*)d_in[3];
    const float* asrc1 = (const float*)d_in[4];
    const float* adst1 = (const float*)d_in[5];
    const float* b1 = (const float*)d_in[6];
    const float* W2 = (const float*)d_in[7];
    const float* asrc2 = (const float*)d_in[8];
    const float* adst2 = (const float*)d_in[9];
    const float* b2 = (const float*)d_in[10];
    const float* fcW = (const float*)d_in[11];
    const float* fcb = (const float*)d_in[12];
    float* out = (float*)d_out;

    detect_k<<<1, 512>>>((const unsigned int*)ei);
    init_k<<<(NN + 255) / 256, 256>>>();

    // CSR build (shared by both layers)
    hist_k<<<(NE + 255) / 256, 256>>>(ei);
    scan1_k<<<NB1, 1024>>>();
    scan2_k<<<1, 32>>>();
    scan3_k<<<NB1, 1024>>>();
    scatter_k<<<(NE + 255) / 256, 256>>>(ei);

    // layer 1
    gemm1_k<<<(NN + 127) / 128, 256>>>(x, W1);
    alpha1_k<<<(NN * 32 + 255) / 256, 256>>>(asrc1, adst1);
    edge1_k<<<(NN * 32 + 255) / 256, 256>>>(b1);

    // layer 2
    gemm2_k<<<(NN + 127) / 128, 128>>>(W2);
    alpha2_k<<<(NN * 16 + 255) / 256, 256>>>(asrc2, adst2);
    edge2_k<<<(NN * 32 + 255) / 256, 256>>>(b2);

    // pool + classifier
    pool_k<<<(NN * 32 + 255) / 256, 256>>>(batch);
    final_k<<<(NG * 32 + 255) / 256, 256>>>(fcW, fcb, out);
}

// round 3
// speedup vs baseline: 1.8159x; 1.0734x over previous
#include <cuda_runtime.h>
#include <cuda_bf16.h>
#include <math.h>

#define NN 50000
#define NE 800000
#define F1 128
#define C2 64
#define NG 512
#define NEG_SLOPE 0.2f
#define NB1 ((NN + 1023) / 1024)

typedef unsigned long long ull;

// ---------------- scratch ----------------
__device__ __align__(16) float g_h1[NN * F1];
__device__ __align__(16) float g_out1[NN * F1];
__device__ __align__(16) float g_h2[NN * C2];
__device__ __align__(16) float g_as1[NN * 2], g_ad1[NN * 2];
__device__ __align__(16) float g_as2[NN], g_ad2[NN];
__device__ __align__(16) float g_pool[NG * C2];
__device__ __align__(16) float g_cnt[NG];
__device__ int g_hist[NN];
__device__ int g_scan[NN];
__device__ int g_cursor[NN];
__device__ int g_off[NN + 1];
__device__ int g_blk[NB1];
__device__ int g_csr[NE];
__device__ int g_is64;

// ---------------- helpers ----------------
__device__ __forceinline__ float lrelu(float x) { return x > 0.f ? x : NEG_SLOPE * x; }

__device__ __forceinline__ ull pack2(float x, float y) {
    ull r; asm("mov.b64 %0, {%1, %2};" : "=l"(r) : "f"(x), "f"(y)); return r;
}
__device__ __forceinline__ void unpack2(ull p, float& x, float& y) {
    asm("mov.b64 {%0, %1}, %2;" : "=f"(x), "=f"(y) : "l"(p));
}
__device__ __forceinline__ void ffma2(ull& acc, ull a, ull b) {
    asm("fma.rn.f32x2 %0, %1, %2, %0;" : "+l"(acc) : "l"(a), "l"(b));
}
__device__ __forceinline__ void redv2(float* dst, float a, float b) {
    asm volatile("red.global.add.v2.f32 [%0], {%1, %2};"
                 :: "l"(dst), "f"(a), "f"(b) : "memory");
}
__device__ __forceinline__ long long loadIdx(const void* p, long long i, int is64) {
    if (is64) return ((const long long*)p)[i];
    return (long long)((const int*)p)[i];
}

// ---------------- init (+ dtype detect in block 0) ----------------
__global__ void init_k(const unsigned int* __restrict__ ei) {
    int i = blockIdx.x * blockDim.x + threadIdx.x;
    if (i < NN) g_hist[i] = 0;
    if (i < NG * C2) g_pool[i] = 0.f;
    if (i < NG) g_cnt[i] = 0.f;
    if (blockIdx.x == 0) {
        __shared__ unsigned int red;
        if (threadIdx.x == 0) red = 0u;
        __syncthreads();
        unsigned int any = 0;
        for (int j = 1 + 2 * threadIdx.x; j < 4096; j += 512) any |= ei[j];
#pragma unroll
        for (int o = 16; o; o >>= 1) any |= __shfl_xor_sync(0xffffffffu, any, o);
        if ((threadIdx.x & 31) == 0) atomicOr(&red, any);
        __syncthreads();
        if (threadIdx.x == 0) g_is64 = (red == 0u) ? 1 : 0;
    }
}

// ---------------- CSR build ----------------
__global__ void hist_k(const void* __restrict__ ei) {
    int e = blockIdx.x * blockDim.x + threadIdx.x;
    if (e >= NE) return;
    int d = (int)loadIdx(ei, (long long)NE + e, g_is64);
    atomicAdd(&g_hist[d], 1);
}

__global__ void scan1_k() {
    __shared__ int ws[32];
    int tid = threadIdx.x, lane = tid & 31, wp = tid >> 5;
    int i = blockIdx.x * 1024 + tid;
    int v = (i < NN) ? g_hist[i] : 0;
#pragma unroll
    for (int o = 1; o < 32; o <<= 1) {
        int t = __shfl_up_sync(0xffffffffu, v, o);
        if (lane >= o) v += t;
    }
    if (lane == 31) ws[wp] = v;
    __syncthreads();
    if (wp == 0) {
        int s = ws[lane];
#pragma unroll
        for (int o = 1; o < 32; o <<= 1) {
            int t = __shfl_up_sync(0xffffffffu, s, o);
            if (lane >= o) s += t;
        }
        ws[lane] = s;
    }
    __syncthreads();
    if (wp > 0) v += ws[wp - 1];
    if (i < NN) g_scan[i] = v;
    if (tid == 1023) g_blk[blockIdx.x] = v;
}

__global__ void scan2_k() {
    if (threadIdx.x == 0) {
        int acc = 0;
        for (int b = 0; b < NB1; b++) { int t = g_blk[b]; g_blk[b] = acc; acc += t; }
    }
}

__global__ void scan3_k() {
    int i = blockIdx.x * 1024 + threadIdx.x;
    if (i >= NN) return;
    int inc = g_scan[i] + g_blk[blockIdx.x];
    g_off[i + 1] = inc;
    g_cursor[i] = inc - g_hist[i];
    if (i == 0) g_off[0] = 0;
}

__global__ void scatter_k(const void* __restrict__ ei) {
    int e = blockIdx.x * blockDim.x + threadIdx.x;
    if (e >= NE) return;
    int is64 = g_is64;
    int s = (int)loadIdx(ei, e, is64);
    int d = (int)loadIdx(ei, (long long)NE + e, is64);
    int pos = atomicAdd(&g_cursor[d], 1);
    g_csr[pos] = s;
}

// -------- GEMM (M x 128) @ (128 x NCOL) + fused alpha dot products ------------
template <int NCOL>
__device__ __forceinline__ void gemm_body(const float* __restrict__ A,
                                          const float* __restrict__ W,
                                          float* __restrict__ Cd,
                                          const float* __restrict__ avs,
                                          const float* __restrict__ avd,
                                          float* __restrict__ as_out,
                                          float* __restrict__ ad_out, int M) {
    constexpr int BM = 128, BK = 16;
    constexpr int TX = NCOL / 8;
    constexpr int NT = 16 * TX;
    constexpr int HEADS = NCOL / 64;
    __shared__ float As[BK][BM];
    __shared__ float Ws[BK][NCOL];
    const int tid = threadIdx.x;
    const int trow = tid / TX, tcol = tid % TX;
    const int row0 = blockIdx.x * BM;
    ull acc[8][4];
#pragma unroll
    for (int m = 0; m < 8; m++)
#pragma unroll
        for (int p = 0; p < 4; p++) acc[m][p] = 0ull;

    for (int kc = 0; kc < 128; kc += BK) {
        for (int i = tid; i < BM * BK / 4; i += NT) {
            int r = i >> 2, q = i & 3;
            float4 v = make_float4(0.f, 0.f, 0.f, 0.f);
            int gr = row0 + r;
            if (gr < M) v = *(const float4*)(A + (size_t)gr * 128 + kc + q * 4);
            As[q * 4 + 0][r] = v.x;
            As[q * 4 + 1][r] = v.y;
            As[q * 4 + 2][r] = v.z;
            As[q * 4 + 3][r] = v.w;
        }
        for (int i = tid; i < BK * NCOL / 4; i += NT) {
            int r = i / (NCOL / 4), c = i % (NCOL / 4);
            *(float4*)&Ws[r][c * 4] = *(const float4*)(W + (size_t)(kc + r) * NCOL + c * 4);
        }
        __syncthreads();
#pragma unroll
        for (int k = 0; k < BK; k++) {
            float4 a0 = *(const float4*)&As[k][trow * 8];
            float4 a1 = *(const float4*)&As[k][trow * 8 + 4];
            float4 w0 = *(const float4*)&Ws[k][tcol * 8];
            float4 w1 = *(const float4*)&Ws[k][tcol * 8 + 4];
            ull wp[4] = {pack2(w0.x, w0.y), pack2(w0.z, w0.w),
                         pack2(w1.x, w1.y), pack2(w1.z, w1.w)};
            float av[8] = {a0.x, a0.y, a0.z, a0.w, a1.x, a1.y, a1.z, a1.w};
#pragma unroll
            for (int m = 0; m < 8; m++) {
                ull ap = pack2(av[m], av[m]);
#pragma unroll
                for (int p = 0; p < 4; p++) ffma2(acc[m][p], ap, wp[p]);
            }
        }
        __syncthreads();
    }

    // alpha vectors for this thread's 8 columns
    float asv[8], adv[8];
#pragma unroll
    for (int p = 0; p < 8; p++) {
        asv[p] = avs[tcol * 8 + p];
        adv[p] = avd[tcol * 8 + p];
    }
    const int hd = (HEADS == 2) ? (tcol >> 3) : 0;

#pragma unroll
    for (int m = 0; m < 8; m++) {
        int gr = row0 + trow * 8 + m;
        float o[8];
#pragma unroll
        for (int p = 0; p < 4; p++) unpack2(acc[m][p], o[2 * p], o[2 * p + 1]);
        float ds = 0.f, dd = 0.f;
#pragma unroll
        for (int p = 0; p < 8; p++) { ds += o[p] * asv[p]; dd += o[p] * adv[p]; }
#pragma unroll
        for (int off = 4; off; off >>= 1) {
            ds += __shfl_xor_sync(0xffffffffu, ds, off);
            dd += __shfl_xor_sync(0xffffffffu, dd, off);
        }
        if (gr < M) {
            *(float4*)(Cd + (size_t)gr * NCOL + tcol * 8) = make_float4(o[0], o[1], o[2], o[3]);
            *(float4*)(Cd + (size_t)gr * NCOL + tcol * 8 + 4) = make_float4(o[4], o[5], o[6], o[7]);
            if ((tcol & 7) == 0) {
                as_out[gr * HEADS + hd] = ds;
                ad_out[gr * HEADS + hd] = dd;
            }
        }
    }
}

__global__ void __launch_bounds__(256) gemm1_k(const float* __restrict__ A,
                                               const float* __restrict__ W,
                                               const float* __restrict__ avs,
                                               const float* __restrict__ avd) {
    gemm_body<128>(A, W, g_h1, avs, avd, g_as1, g_ad1, NN);
}
__global__ void __launch_bounds__(128) gemm2_k(const float* __restrict__ W,
                                               const float* __restrict__ avs,
                                               const float* __restrict__ avd) {
    gemm_body<64>(g_out1, W, g_h2, avs, avd, g_as2, g_ad2, NN);
}

// ------- fused single-sweep softmax + aggregate, layer 1 (warp per dst) -------
__global__ void __launch_bounds__(256) edge1_k(const float* __restrict__ b1) {
    int d = (blockIdx.x * blockDim.x + threadIdx.x) >> 5;
    int lane = threadIdx.x & 31;
    if (d >= NN) return;
    int beg = g_off[d], end = g_off[d + 1];
    float2 adp = *(const float2*)(g_ad1 + d * 2);
    const bool h0 = lane < 16;
    float adh = h0 ? adp.x : adp.y;

    float4 acc = make_float4(0.f, 0.f, 0.f, 0.f);
    float csum = 0.f;

    int j = beg;
    for (; j + 1 < end; j += 2) {
        int sA = g_csr[j], sB = g_csr[j + 1];
        float2 aA = *(const float2*)(g_as1 + sA * 2);
        float2 aB = *(const float2*)(g_as1 + sB * 2);
        float4 hA = *(const float4*)(g_h1 + (size_t)sA * 128 + lane * 4);
        float4 hB = *(const float4*)(g_h1 + (size_t)sB * 128 + lane * 4);
        float cA = __expf(lrelu((h0 ? aA.x : aA.y) + adh));
        float cB = __expf(lrelu((h0 ? aB.x : aB.y) + adh));
        csum += cA + cB;
        acc.x += cA * hA.x + cB * hB.x;
        acc.y += cA * hA.y + cB * hB.y;
        acc.z += cA * hA.z + cB * hB.z;
        acc.w += cA * hA.w + cB * hB.w;
    }
    if (j < end) {
        int s = g_csr[j];
        float2 as = *(const float2*)(g_as1 + s * 2);
        float4 hv = *(const float4*)(g_h1 + (size_t)s * 128 + lane * 4);
        float c = __expf(lrelu((h0 ? as.x : as.y) + adh));
        csum += c;
        acc.x += c * hv.x; acc.y += c * hv.y; acc.z += c * hv.z; acc.w += c * hv.w;
    }
    // self loop
    {
        float2 asd = *(const float2*)(g_as1 + d * 2);
        float4 hv = *(const float4*)(g_h1 + (size_t)d * 128 + lane * 4);
        float c = __expf(lrelu((h0 ? asd.x : asd.y) + adh));
        csum += c;
        acc.x += c * hv.x; acc.y += c * hv.y; acc.z += c * hv.z; acc.w += c * hv.w;
    }
    float inv = 1.f / csum;   // identical across lanes of a head-half
    float4 b = *(const float4*)(b1 + lane * 4);
    *(float4*)(g_out1 + (size_t)d * 128 + lane * 4) =
        make_float4(fmaxf(acc.x * inv + b.x, 0.f), fmaxf(acc.y * inv + b.y, 0.f),
                    fmaxf(acc.z * inv + b.z, 0.f), fmaxf(acc.w * inv + b.w, 0.f));
}

// ------- fused single-sweep layer 2 + direct pooling ---------------------------
__global__ void __launch_bounds__(256) edge2_k(const float* __restrict__ b2,
                                               const void* __restrict__ batch) {
    int d = (blockIdx.x * blockDim.x + threadIdx.x) >> 5;
    int lane = threadIdx.x & 31;
    if (d >= NN) return;
    int beg = g_off[d], end = g_off[d + 1];
    float ad = g_ad2[d];

    float2 acc = make_float2(0.f, 0.f);
    float csum = 0.f;

    int j = beg;
    for (; j + 1 < end; j += 2) {
        int sA = g_csr[j], sB = g_csr[j + 1];
        float aA = g_as2[sA], aB = g_as2[sB];
        float2 hA = *(const float2*)(g_h2 + (size_t)sA * 64 + lane * 2);
        float2 hB = *(const float2*)(g_h2 + (size_t)sB * 64 + lane * 2);
        float cA = __expf(lrelu(aA + ad));
        float cB = __expf(lrelu(aB + ad));
        csum += cA + cB;
        acc.x += cA * hA.x + cB * hB.x;
        acc.y += cA * hA.y + cB * hB.y;
    }
    if (j < end) {
        int s = g_csr[j];
        float2 hv = *(const float2*)(g_h2 + (size_t)s * 64 + lane * 2);
        float c = __expf(lrelu(g_as2[s] + ad));
        csum += c;
        acc.x += c * hv.x; acc.y += c * hv.y;
    }
    {
        float2 hv = *(const float2*)(g_h2 + (size_t)d * 64 + lane * 2);
        float c = __expf(lrelu(g_as2[d] + ad));
        csum += c;
        acc.x += c * hv.x; acc.y += c * hv.y;
    }
    float inv = 1.f / csum;
    float2 b = *(const float2*)(b2 + lane * 2);
    float r0 = fmaxf(acc.x * inv + b.x, 0.f);
    float r1 = fmaxf(acc.y * inv + b.y, 0.f);

    int bg = (int)loadIdx(batch, d, g_is64);
    redv2(g_pool + (size_t)bg * 64 + lane * 2, r0, r1);
    if (!lane) atomicAdd(g_cnt + bg, 1.f);
}

// ---------------- final FC + log_softmax ----------------
__global__ void final_k(const float* __restrict__ fcW, const float* __restrict__ fcb,
                        float* __restrict__ out) {
    int gw = (blockIdx.x * blockDim.x + threadIdx.x) >> 5;
    int lane = threadIdx.x & 31;
    if (gw >= NG) return;
    float inv = 1.f / fmaxf(g_cnt[gw], 1.f);
    float p0 = g_pool[(size_t)gw * 64 + lane] * inv;
    float p1 = g_pool[(size_t)gw * 64 + 32 + lane] * inv;
    float l0 = p0 * fcW[lane * 2] + p1 * fcW[(lane + 32) * 2];
    float l1 = p0 * fcW[lane * 2 + 1] + p1 * fcW[(lane + 32) * 2 + 1];
#pragma unroll
    for (int o = 16; o; o >>= 1) {
        l0 += __shfl_xor_sync(0xffffffffu, l0, o);
        l1 += __shfl_xor_sync(0xffffffffu, l1, o);
    }
    if (!lane) {
        l0 += fcb[0];
        l1 += fcb[1];
        float m = fmaxf(l0, l1);
        float lse = m + logf(expf(l0 - m) + expf(l1 - m));
        out[gw * 2] = l0 - lse;
        out[gw * 2 + 1] = l1 - lse;
    }
}

// ---------------- launch ----------------
extern "C" void kernel_launch(void* const* d_in, const int* in_sizes, int n_in,
                              void* d_out, int out_size) {
    const float* x = (const float*)d_in[0];
    const void* ei = d_in[1];
    const void* batch = d_in[2];
    const float* W1 = (const float*)d_in[3];
    const float* asrc1 = (const float*)d_in[4];
    const float* adst1 = (const float*)d_in[5];
    const float* b1 = (const float*)d_in[6];
    const float* W2 = (const float*)d_in[7];
    const float* asrc2 = (const float*)d_in[8];
    const float* adst2 = (const float*)d_in[9];
    const float* b2 = (const float*)d_in[10];
    const float* fcW = (const float*)d_in[11];
    const float* fcb = (const float*)d_in[12];
    float* out = (float*)d_out;

    init_k<<<(NN + 255) / 256, 256>>>((const unsigned int*)ei);

    // CSR build (shared by both layers)
    hist_k<<<(NE + 255) / 256, 256>>>(ei);
    scan1_k<<<NB1, 1024>>>();
    scan2_k<<<1, 32>>>();
    scan3_k<<<NB1, 1024>>>();
    scatter_k<<<(NE + 255) / 256, 256>>>(ei);

    // layer 1
    gemm1_k<<<(NN + 127) / 128, 256>>>(x, W1, asrc1, adst1);
    edge1_k<<<(NN * 32 + 255) / 256, 256>>>(b1);

    // layer 2
    gemm2_k<<<(NN + 127) / 128, 128>>>(W2, asrc2, adst2);
    edge2_k<<<(NN * 32 + 255) / 256, 256>>>(b2, batch);

    // classifier
    final_k<<<(NG * 32 + 255) / 256, 256>>>(fcW, fcb, out);
}

// round 4
// speedup vs baseline: 2.0250x; 1.1152x over previous
#include <cuda_runtime.h>
#include <cuda_bf16.h>
#include <math.h>

#define NN 50000
#define NE 800000
#define F1 128
#define C2 64
#define NG 512
#define NEG_SLOPE 0.2f
#define NB1 ((NN + 1023) / 1024)

typedef unsigned long long ull;

// ---------------- scratch ----------------
__device__ __align__(16) float g_h1[NN * F1];
__device__ __align__(16) float g_out1[NN * F1];
__device__ __align__(16) float g_h2[NN * C2];
__device__ __align__(16) float g_as1[NN * 2], g_ad1[NN * 2];
__device__ __align__(16) float g_as2[NN], g_ad2[NN];
__device__ __align__(16) float g_pool[NG * C2];
__device__ __align__(16) float g_cnt[NG];
__device__ int g_hist[NN];
__device__ int g_cursor[NN];
__device__ int g_off[NN + 1];
__device__ int g_csr[NE];
__device__ int g_is64;
// decoupled-lookback scan state
__device__ int g_scanctr;
__device__ int g_bflag[NB1];
__device__ int g_bagg[NB1];
__device__ int g_binc[NB1];

// ---------------- helpers ----------------
__device__ __forceinline__ float lrelu(float x) { return x > 0.f ? x : NEG_SLOPE * x; }

__device__ __forceinline__ ull pack2(float x, float y) {
    ull r; asm("mov.b64 %0, {%1, %2};" : "=l"(r) : "f"(x), "f"(y)); return r;
}
__device__ __forceinline__ void unpack2(ull p, float& x, float& y) {
    asm("mov.b64 {%0, %1}, %2;" : "=f"(x), "=f"(y) : "l"(p));
}
__device__ __forceinline__ void ffma2(ull& acc, ull a, ull b) {
    asm("fma.rn.f32x2 %0, %1, %2, %0;" : "+l"(acc) : "l"(a), "l"(b));
}
__device__ __forceinline__ void redv2(float* dst, float a, float b) {
    asm volatile("red.global.add.v2.f32 [%0], {%1, %2};"
                 :: "l"(dst), "f"(a), "f"(b) : "memory");
}
__device__ __forceinline__ long long loadIdx(const void* p, long long i, int is64) {
    if (is64) return ((const long long*)p)[i];
    return (long long)((const int*)p)[i];
}

// ---------------- init (+ dtype detect in block 0) ----------------
__global__ void init_k(const unsigned int* __restrict__ ei) {
    int i = blockIdx.x * blockDim.x + threadIdx.x;
    if (i < NN) g_hist[i] = 0;
    if (i < NG * C2) g_pool[i] = 0.f;
    if (i < NG) g_cnt[i] = 0.f;
    if (i < NB1) { g_bflag[i] = 0; }
    if (i == 0) g_scanctr = 0;
    if (blockIdx.x == 0) {
        __shared__ unsigned int red;
        if (threadIdx.x == 0) red = 0u;
        __syncthreads();
        unsigned int any = 0;
        for (int j = 1 + 2 * threadIdx.x; j < 4096; j += 512) any |= ei[j];
#pragma unroll
        for (int o = 16; o; o >>= 1) any |= __shfl_xor_sync(0xffffffffu, any, o);
        if ((threadIdx.x & 31) == 0) atomicOr(&red, any);
        __syncthreads();
        if (threadIdx.x == 0) g_is64 = (red == 0u) ? 1 : 0;
    }
}

// ---------------- CSR build ----------------
__global__ void hist_k(const void* __restrict__ ei) {
    int e = blockIdx.x * blockDim.x + threadIdx.x;
    if (e >= NE) return;
    int d = (int)loadIdx(ei, (long long)NE + e, g_is64);
    atomicAdd(&g_hist[d], 1);
}

// single-pass decoupled-lookback scan: fills g_off[] and g_cursor[]
__global__ void __launch_bounds__(1024) scan_k() {
    __shared__ int ws[32];
    __shared__ int sbid, sprefix;
    int tid = threadIdx.x, lane = tid & 31, wp = tid >> 5;
    if (tid == 0) sbid = atomicAdd(&g_scanctr, 1);
    __syncthreads();
    int bid = sbid;
    int i = bid * 1024 + tid;
    int hv = (i < NN) ? g_hist[i] : 0;
    int v = hv;
#pragma unroll
    for (int o = 1; o < 32; o <<= 1) {
        int t = __shfl_up_sync(0xffffffffu, v, o);
        if (lane >= o) v += t;
    }
    if (lane == 31) ws[wp] = v;
    __syncthreads();
    if (wp == 0) {
        int s = ws[lane];
#pragma unroll
        for (int o = 1; o < 32; o <<= 1) {
            int t = __shfl_up_sync(0xffffffffu, s, o);
            if (lane >= o) s += t;
        }
        ws[lane] = s;
    }
    __syncthreads();
    if (wp > 0) v += ws[wp - 1];     // v = inclusive scan within block

    if (tid == 1023) {
        if (bid == 0) { g_binc[0] = v; __threadfence(); g_bflag[0] = 2; }
        else          { g_bagg[bid] = v; __threadfence(); g_bflag[bid] = 1; }
    }
    if (tid == 0) {
        int run = 0;
        if (bid > 0) {
            int p = bid - 1;
            while (true) {
                int f;
                do { f = ((volatile int*)g_bflag)[p]; } while (f == 0);
                __threadfence();
                if (f == 2) { run += ((volatile int*)g_binc)[p]; break; }
                run += ((volatile int*)g_bagg)[p];
                p--;
            }
        }
        sprefix = run;
    }
    __syncthreads();
    int pre = sprefix;
    if (tid == 1023 && bid > 0) {
        g_binc[bid] = pre + v; __threadfence(); g_bflag[bid] = 2;
    }
    int inc = pre + v;
    if (i < NN) {
        g_off[i + 1] = inc;
        g_cursor[i] = inc - hv;
    }
    if (i == 0) g_off[0] = 0;
}

__global__ void scatter_k(const void* __restrict__ ei) {
    int e = blockIdx.x * blockDim.x + threadIdx.x;
    if (e >= NE) return;
    int is64 = g_is64;
    int s = (int)loadIdx(ei, e, is64);
    int d = (int)loadIdx(ei, (long long)NE + e, is64);
    int pos = atomicAdd(&g_cursor[d], 1);
    g_csr[pos] = s;
}

// -------- GEMM (M x 128) @ (128 x NCOL) + fused alpha dot products ------------
template <int NCOL>
__device__ __forceinline__ void gemm_body(const float* __restrict__ A,
                                          const float* __restrict__ W,
                                          float* __restrict__ Cd,
                                          const float* __restrict__ avs,
                                          const float* __restrict__ avd,
                                          float* __restrict__ as_out,
                                          float* __restrict__ ad_out, int M) {
    constexpr int BM = 128, BK = 16;
    constexpr int TX = NCOL / 8;
    constexpr int NT = 16 * TX;
    constexpr int HEADS = NCOL / 64;
    __shared__ float As[BK][BM];
    __shared__ float Ws[BK][NCOL];
    const int tid = threadIdx.x;
    const int trow = tid / TX, tcol = tid % TX;
    const int row0 = blockIdx.x * BM;
    ull acc[8][4];
#pragma unroll
    for (int m = 0; m < 8; m++)
#pragma unroll
        for (int p = 0; p < 4; p++) acc[m][p] = 0ull;

    for (int kc = 0; kc < 128; kc += BK) {
        for (int i = tid; i < BM * BK / 4; i += NT) {
            int r = i >> 2, q = i & 3;
            float4 v = make_float4(0.f, 0.f, 0.f, 0.f);
            int gr = row0 + r;
            if (gr < M) v = *(const float4*)(A + (size_t)gr * 128 + kc + q * 4);
            As[q * 4 + 0][r] = v.x;
            As[q * 4 + 1][r] = v.y;
            As[q * 4 + 2][r] = v.z;
            As[q * 4 + 3][r] = v.w;
        }
        for (int i = tid; i < BK * NCOL / 4; i += NT) {
            int r = i / (NCOL / 4), c = i % (NCOL / 4);
            *(float4*)&Ws[r][c * 4] = *(const float4*)(W + (size_t)(kc + r) * NCOL + c * 4);
        }
        __syncthreads();
#pragma unroll
        for (int k = 0; k < BK; k++) {
            float4 a0 = *(const float4*)&As[k][trow * 8];
            float4 a1 = *(const float4*)&As[k][trow * 8 + 4];
            float4 w0 = *(const float4*)&Ws[k][tcol * 8];
            float4 w1 = *(const float4*)&Ws[k][tcol * 8 + 4];
            ull wp[4] = {pack2(w0.x, w0.y), pack2(w0.z, w0.w),
                         pack2(w1.x, w1.y), pack2(w1.z, w1.w)};
            float av[8] = {a0.x, a0.y, a0.z, a0.w, a1.x, a1.y, a1.z, a1.w};
#pragma unroll
            for (int m = 0; m < 8; m++) {
                ull ap = pack2(av[m], av[m]);
#pragma unroll
                for (int p = 0; p < 4; p++) ffma2(acc[m][p], ap, wp[p]);
            }
        }
        __syncthreads();
    }

    float asv[8], adv[8];
#pragma unroll
    for (int p = 0; p < 8; p++) {
        asv[p] = avs[tcol * 8 + p];
        adv[p] = avd[tcol * 8 + p];
    }
    const int hd = (HEADS == 2) ? (tcol >> 3) : 0;

#pragma unroll
    for (int m = 0; m < 8; m++) {
        int gr = row0 + trow * 8 + m;
        float o[8];
#pragma unroll
        for (int p = 0; p < 4; p++) unpack2(acc[m][p], o[2 * p], o[2 * p + 1]);
        float ds = 0.f, dd = 0.f;
#pragma unroll
        for (int p = 0; p < 8; p++) { ds += o[p] * asv[p]; dd += o[p] * adv[p]; }
#pragma unroll
        for (int off = 4; off; off >>= 1) {
            ds += __shfl_xor_sync(0xffffffffu, ds, off);
            dd += __shfl_xor_sync(0xffffffffu, dd, off);
        }
        if (gr < M) {
            *(float4*)(Cd + (size_t)gr * NCOL + tcol * 8) = make_float4(o[0], o[1], o[2], o[3]);
            *(float4*)(Cd + (size_t)gr * NCOL + tcol * 8 + 4) = make_float4(o[4], o[5], o[6], o[7]);
            if ((tcol & 7) == 0) {
                as_out[gr * HEADS + hd] = ds;
                ad_out[gr * HEADS + hd] = dd;
            }
        }
    }
}

__global__ void __launch_bounds__(256) gemm1_k(const float* __restrict__ A,
                                               const float* __restrict__ W,
                                               const float* __restrict__ avs,
                                               const float* __restrict__ avd) {
    gemm_body<128>(A, W, g_h1, avs, avd, g_as1, g_ad1, NN);
}
__global__ void __launch_bounds__(128) gemm2_k(const float* __restrict__ W,
                                               const float* __restrict__ avs,
                                               const float* __restrict__ avd) {
    gemm_body<64>(g_out1, W, g_h2, avs, avd, g_as2, g_ad2, NN);
}

// ------- fused single-sweep softmax + aggregate, layer 1 (warp per dst) -------
__global__ void __launch_bounds__(256) edge1_k(const float* __restrict__ b1) {
    int d = (blockIdx.x * blockDim.x + threadIdx.x) >> 5;
    int lane = threadIdx.x & 31;
    if (d >= NN) return;
    int beg = g_off[d], end = g_off[d + 1];
    float2 adp = *(const float2*)(g_ad1 + d * 2);
    const bool h0 = lane < 16;
    float adh = h0 ? adp.x : adp.y;

    float4 acc = make_float4(0.f, 0.f, 0.f, 0.f);
    float csum = 0.f;

    int j = beg;
    for (; j + 1 < end; j += 2) {
        int sA = g_csr[j], sB = g_csr[j + 1];
        float2 aA = *(const float2*)(g_as1 + sA * 2);
        float2 aB = *(const float2*)(g_as1 + sB * 2);
        float4 hA = *(const float4*)(g_h1 + (size_t)sA * 128 + lane * 4);
        float4 hB = *(const float4*)(g_h1 + (size_t)sB * 128 + lane * 4);
        float cA = __expf(lrelu((h0 ? aA.x : aA.y) + adh));
        float cB = __expf(lrelu((h0 ? aB.x : aB.y) + adh));
        csum += cA + cB;
        acc.x += cA * hA.x + cB * hB.x;
        acc.y += cA * hA.y + cB * hB.y;
        acc.z += cA * hA.z + cB * hB.z;
        acc.w += cA * hA.w + cB * hB.w;
    }
    if (j < end) {
        int s = g_csr[j];
        float2 as = *(const float2*)(g_as1 + s * 2);
        float4 hv = *(const float4*)(g_h1 + (size_t)s * 128 + lane * 4);
        float c = __expf(lrelu((h0 ? as.x : as.y) + adh));
        csum += c;
        acc.x += c * hv.x; acc.y += c * hv.y; acc.z += c * hv.z; acc.w += c * hv.w;
    }
    {
        float2 asd = *(const float2*)(g_as1 + d * 2);
        float4 hv = *(const float4*)(g_h1 + (size_t)d * 128 + lane * 4);
        float c = __expf(lrelu((h0 ? asd.x : asd.y) + adh));
        csum += c;
        acc.x += c * hv.x; acc.y += c * hv.y; acc.z += c * hv.z; acc.w += c * hv.w;
    }
    float inv = 1.f / csum;
    float4 b = *(const float4*)(b1 + lane * 4);
    *(float4*)(g_out1 + (size_t)d * 128 + lane * 4) =
        make_float4(fmaxf(acc.x * inv + b.x, 0.f), fmaxf(acc.y * inv + b.y, 0.f),
                    fmaxf(acc.z * inv + b.z, 0.f), fmaxf(acc.w * inv + b.w, 0.f));
}

// ------- fused single-sweep layer 2 + direct pooling ---------------------------
__global__ void __launch_bounds__(256) edge2_k(const float* __restrict__ b2,
                                               const void* __restrict__ batch) {
    int d = (blockIdx.x * blockDim.x + threadIdx.x) >> 5;
    int lane = threadIdx.x & 31;
    if (d >= NN) return;
    int beg = g_off[d], end = g_off[d + 1];
    float ad = g_ad2[d];

    float2 acc = make_float2(0.f, 0.f);
    float csum = 0.f;

    int j = beg;
    for (; j + 1 < end; j += 2) {
        int sA = g_csr[j], sB = g_csr[j + 1];
        float aA = g_as2[sA], aB = g_as2[sB];
        float2 hA = *(const float2*)(g_h2 + (size_t)sA * 64 + lane * 2);
        float2 hB = *(const float2*)(g_h2 + (size_t)sB * 64 + lane * 2);
        float cA = __expf(lrelu(aA + ad));
        float cB = __expf(lrelu(aB + ad));
        csum += cA + cB;
        acc.x += cA * hA.x + cB * hB.x;
        acc.y += cA * hA.y + cB * hB.y;
    }
    if (j < end) {
        int s = g_csr[j];
        float2 hv = *(const float2*)(g_h2 + (size_t)s * 64 + lane * 2);
        float c = __expf(lrelu(g_as2[s] + ad));
        csum += c;
        acc.x += c * hv.x; acc.y += c * hv.y;
    }
    {
        float2 hv = *(const float2*)(g_h2 + (size_t)d * 64 + lane * 2);
        float c = __expf(lrelu(g_as2[d] + ad));
        csum += c;
        acc.x += c * hv.x; acc.y += c * hv.y;
    }
    float inv = 1.f / csum;
    float2 b = *(const float2*)(b2 + lane * 2);
    float r0 = fmaxf(acc.x * inv + b.x, 0.f);
    float r1 = fmaxf(acc.y * inv + b.y, 0.f);

    int bg = (int)loadIdx(batch, d, g_is64);
    redv2(g_pool + (size_t)bg * 64 + lane * 2, r0, r1);
    if (!lane) atomicAdd(g_cnt + bg, 1.f);
}

// ---------------- final FC + log_softmax ----------------
__global__ void final_k(const float* __restrict__ fcW, const float* __restrict__ fcb,
                        float* __restrict__ out) {
    int gw = (blockIdx.x * blockDim.x + threadIdx.x) >> 5;
    int lane = threadIdx.x & 31;
    if (gw >= NG) return;
    float inv = 1.f / fmaxf(g_cnt[gw], 1.f);
    float p0 = g_pool[(size_t)gw * 64 + lane] * inv;
    float p1 = g_pool[(size_t)gw * 64 + 32 + lane] * inv;
    float l0 = p0 * fcW[lane * 2] + p1 * fcW[(lane + 32) * 2];
    float l1 = p0 * fcW[lane * 2 + 1] + p1 * fcW[(lane + 32) * 2 + 1];
#pragma unroll
    for (int o = 16; o; o >>= 1) {
        l0 += __shfl_xor_sync(0xffffffffu, l0, o);
        l1 += __shfl_xor_sync(0xffffffffu, l1, o);
    }
    if (!lane) {
        l0 += fcb[0];
        l1 += fcb[1];
        float m = fmaxf(l0, l1);
        float lse = m + logf(expf(l0 - m) + expf(l1 - m));
        out[gw * 2] = l0 - lse;
        out[gw * 2 + 1] = l1 - lse;
    }
}

// ---------------- launch ----------------
extern "C" void kernel_launch(void* const* d_in, const int* in_sizes, int n_in,
                              void* d_out, int out_size) {
    const float* x = (const float*)d_in[0];
    const void* ei = d_in[1];
    const void* batch = d_in[2];
    const float* W1 = (const float*)d_in[3];
    const float* asrc1 = (const float*)d_in[4];
    const float* adst1 = (const float*)d_in[5];
    const float* b1 = (const float*)d_in[6];
    const float* W2 = (const float*)d_in[7];
    const float* asrc2 = (const float*)d_in[8];
    const float* adst2 = (const float*)d_in[9];
    const float* b2 = (const float*)d_in[10];
    const float* fcW = (const float*)d_in[11];
    const float* fcb = (const float*)d_in[12];
    float* out = (float*)d_out;

    // one-time host-side objects (no device memory)
    static cudaStream_t s2 = nullptr;
    static cudaEvent_t evA = nullptr, evB = nullptr;
    if (!s2) {
        cudaStreamCreateWithFlags(&s2, cudaStreamNonBlocking);
        cudaEventCreateWithFlags(&evA, cudaEventDisableTiming);
        cudaEventCreateWithFlags(&evB, cudaEventDisableTiming);
    }

    // fork: CSR build on s2, gemm1 on main stream (both captured)
    cudaEventRecord(evA, 0);
    cudaStreamWaitEvent(s2, evA, 0);

    init_k<<<(NN + 255) / 256, 256, 0, s2>>>((const unsigned int*)ei);
    hist_k<<<(NE + 255) / 256, 256, 0, s2>>>(ei);
    scan_k<<<NB1, 1024, 0, s2>>>();
    scatter_k<<<(NE + 255) / 256, 256, 0, s2>>>(ei);
    cudaEventRecord(evB, s2);

    gemm1_k<<<(NN + 127) / 128, 256>>>(x, W1, asrc1, adst1);

    // join
    cudaStreamWaitEvent(0, evB, 0);

    edge1_k<<<(NN * 32 + 255) / 256, 256>>>(b1);
    gemm2_k<<<(NN + 127) / 128, 128>>>(W2, asrc2, adst2);
    edge2_k<<<(NN * 32 + 255) / 256, 256>>>(b2, batch);
    final_k<<<(NG * 32 + 255) / 256, 256>>>(fcW, fcb, out);
}